// round 10
// baseline (speedup 1.0000x reference)
#include <cuda_runtime.h>
#include <cuda_bf16.h>
#include <math.h>
#include <stdint.h>

// Problem constants (fixed by the reference: B=4096, D=1024, N_CLASSES=64)
#define NB 4096
#define ND 1024

#define MARGIN    0.09f
#define SCALE_POS 2.0f
#define SCALE_NEG 40.0f
#define EPS_C     1e-5f
#define THRESH1   0.501f
#define THRESH2   0.531f
#define POS_SLOTS 256

// -------------------- device scratch (no runtime allocation) --------------------
__device__ float g_t32[(size_t)NB * ND];            // 16 MB tf32-rounded feats
__device__ int   g_labels[NB];
__device__ float g_negsum[NB];
__device__ int   g_nneg[NB];
__device__ float g_maxE[NB];                        // max over negs of exp(40*sim)
__device__ int   g_poscnt[NB];
__device__ float g_posval[(size_t)NB * POS_SLOTS];  // 4 MB pos-candidate sims
__device__ float g_row[NB];

// -------------------- PTX helpers (plain sm_80 features only) --------------------
__device__ __forceinline__ uint32_t smem_u32(const void* p) {
    uint32_t a;
    asm("{ .reg .u64 t; cvta.to.shared.u64 t, %1; cvt.u32.u64 %0, t; }" : "=r"(a) : "l"(p));
    return a;
}
__device__ __forceinline__ void cp16(uint32_t s, const void* g) {
    asm volatile("cp.async.cg.shared.global [%0], [%1], 16;" :: "r"(s), "l"(g));
}
#define CP_COMMIT() asm volatile("cp.async.commit_group;" ::: "memory")
#define CP_WAIT2()  asm volatile("cp.async.wait_group 2;" ::: "memory")

__device__ __forceinline__ void ldsm4(uint32_t* r, uint32_t addr) {
    asm volatile("ldmatrix.sync.aligned.m8n8.x4.shared.b16 {%0,%1,%2,%3}, [%4];"
                 : "=r"(r[0]), "=r"(r[1]), "=r"(r[2]), "=r"(r[3]) : "r"(addr));
}
// m16n8k8 tf32: A = 4 regs, B = 2 regs, fp32 accum
__device__ __forceinline__ void mma_tf32(float* d, const uint32_t* a,
                                         uint32_t b0, uint32_t b1) {
    asm volatile(
        "mma.sync.aligned.m16n8k8.row.col.f32.tf32.tf32.f32 "
        "{%0,%1,%2,%3}, {%4,%5,%6,%7}, {%8,%9}, {%0,%1,%2,%3};"
        : "+f"(d[0]), "+f"(d[1]), "+f"(d[2]), "+f"(d[3])
        : "r"(a[0]), "r"(a[1]), "r"(a[2]), "r"(a[3]), "r"(b0), "r"(b1));
}
__device__ __forceinline__ uint32_t to_tf32(float x) {
    uint32_t o;
    asm("cvt.rna.tf32.f32 %0, %1;" : "=r"(o) : "f"(x));
    return o;
}

// -------------------- kernel 0: labels (dtype auto-detect) + stat init --------------------
__global__ void __launch_bounds__(256) labels_kernel(const int* __restrict__ lab) {
    __shared__ int sred[256];
    __shared__ int s_is64;
    int tid = threadIdx.x;
    int acc = 0;
    for (int i = tid; i < 2048; i += 256) acc |= lab[2 * i + 1];
    sred[tid] = acc;
    __syncthreads();
    for (int o = 128; o > 0; o >>= 1) {
        if (tid < o) sred[tid] |= sred[tid + o];
        __syncthreads();
    }
    if (tid == 0) s_is64 = (sred[0] == 0) ? 1 : 0;
    __syncthreads();
    int is64 = s_is64;
    for (int i = tid; i < NB; i += 256) {
        g_labels[i] = is64 ? lab[2 * i] : lab[i];
        g_negsum[i] = 0.0f;
        g_nneg[i]   = 0;
        g_maxE[i]   = 0.0f;
        g_poscnt[i] = 0;
    }
}

// -------------------- kernel 1: f32 -> tf32 (round-to-nearest) --------------------
__global__ void __launch_bounds__(512) convert_kernel(const float* __restrict__ F) {
    size_t i = (size_t)blockIdx.x * 512 + threadIdx.x;   // one float4 per thread
    float4 v = reinterpret_cast<const float4*>(F)[i];
    uint4 o;
    o.x = to_tf32(v.x);
    o.y = to_tf32(v.y);
    o.z = to_tf32(v.z);
    o.w = to_tf32(v.w);
    reinterpret_cast<uint4*>(g_t32)[i] = o;
}

// -------------------- kernel 2: tf32 GEMM with fused loss-stat epilogue --------------------
// 128x128 tiles, upper triangle; 4 warps x (64x64); BK=32 f32; 3-stage cp.async.
// Epilogue computes neg stats (both orientations) + pos candidate lists directly
// from accumulators; no sim matrix is ever materialized.
#define STAGE_BYTES 32768          // A 16KB + B 16KB
#define NCHUNK 32
#define DYNSMEM (3 * STAGE_BYTES)  // 96 KB (epilogue reuses 64 KB for exp tile)

__device__ __forceinline__ void load_chunk(int c, uint32_t stage,
                                           int rowA, int rowB, int tid) {
    const uint8_t* base = reinterpret_cast<const uint8_t*>(g_t32);
    size_t k0 = (size_t)c * 128;     // byte offset within 4096B row
    uint32_t sB = stage + 16384;
#pragma unroll
    for (int j = 0; j < 8; j++) {
        int u = (j << 7) + tid;          // 0..1023 16B units per operand
        int r = u >> 3;                  // row 0..127
        int ch = u & 7;                  // 16B chunk within 128B row
        uint32_t off = (uint32_t)((r << 7) + (ch << 4));
        uint32_t sw = off ^ ((off >> 3) & 0x70);
        cp16(stage + sw, base + (size_t)(rowA + r) * 4096 + k0 + (ch << 4));
        cp16(sB + sw,    base + (size_t)(rowB + r) * 4096 + k0 + (ch << 4));
    }
}

__global__ void __launch_bounds__(128, 2) gemm_mma_kernel() {
    extern __shared__ char dsm[];
    if ((int)blockIdx.x < (int)blockIdx.y) return;   // upper triangle only
    const int tid = threadIdx.x;
    const int lid = tid & 31;
    const int wid = tid >> 5;            // 0..3
    const int tileRow = blockIdx.y * 128;
    const int tileCol = blockIdx.x * 128;
    const bool diag = (blockIdx.x == blockIdx.y);

    uint32_t SB = (smem_u32(dsm) + 127u) & ~127u;

    // warp tile: 64 (M) x 64 (N); warp grid 2 x 2
    const int mRow0 = (wid >> 1) * 64;
    const int nCol0 = (wid & 1) * 64;

    // ldmatrix lane addressing (b16-view of f32 tiles)
    const int aRow  = lid & 15;
    const int aKoff = ((lid >> 4) & 1) * 16;         // bytes
    const int bRow  = (lid & 7) + ((lid >> 4) << 3);
    const int bKoff = ((lid >> 3) & 1) * 16;         // bytes

    float acc[4][8][4];
#pragma unroll
    for (int mt = 0; mt < 4; mt++)
#pragma unroll
        for (int nt = 0; nt < 8; nt++)
#pragma unroll
            for (int q = 0; q < 4; q++) acc[mt][nt][q] = 0.0f;

    load_chunk(0, SB + 0 * STAGE_BYTES, tileRow, tileCol, tid); CP_COMMIT();
    load_chunk(1, SB + 1 * STAGE_BYTES, tileRow, tileCol, tid); CP_COMMIT();

    for (int c = 0; c < NCHUNK; c++) {
        if (c + 2 < NCHUNK)
            load_chunk(c + 2, SB + ((c + 2) % 3) * STAGE_BYTES, tileRow, tileCol, tid);
        CP_COMMIT();
        CP_WAIT2();
        __syncthreads();

        uint32_t sa = SB + (c % 3) * STAGE_BYTES;
        uint32_t sbm = sa + 16384;
#pragma unroll
        for (int kk = 0; kk < 4; kk++) {             // 4 x k8 within BK=32 f32
            uint32_t afrag[4][4];
#pragma unroll
            for (int mt = 0; mt < 4; mt++) {
                uint32_t off = (uint32_t)((mRow0 + mt * 16 + aRow) * 128 +
                                          aKoff + kk * 32);
                ldsm4(afrag[mt], sa + (off ^ ((off >> 3) & 0x70)));
            }
            uint32_t bfrag[4][4];                     // each g: n16 (two n8 frags)
#pragma unroll
            for (int g = 0; g < 4; g++) {
                uint32_t off = (uint32_t)((nCol0 + g * 16 + bRow) * 128 +
                                          bKoff + kk * 32);
                ldsm4(bfrag[g], sbm + (off ^ ((off >> 3) & 0x70)));
            }
#pragma unroll
            for (int mt = 0; mt < 4; mt++)
#pragma unroll
                for (int g = 0; g < 4; g++) {
                    mma_tf32(acc[mt][g * 2],     afrag[mt], bfrag[g][0], bfrag[g][1]);
                    mma_tf32(acc[mt][g * 2 + 1], afrag[mt], bfrag[g][2], bfrag[g][3]);
                }
        }
        __syncthreads();
    }

    // ================= fused stats epilogue =================
    // Fragment element map (verified in prior epilogue): acc[mt][nt][h*2+q2] is
    //   row  = mRow0 + mt*16 + (lid>>2) + h*8      (tile-local)
    //   col  = nCol0 + nt*8 + (lid&3)*2 + q2       (tile-local)
    float* C = reinterpret_cast<float*>(dsm);
    const int rhi = lid >> 2;
    const int clo = (lid & 3) * 2;

    int clab[16];
#pragma unroll
    for (int nt = 0; nt < 8; nt++) {
        clab[nt * 2]     = g_labels[tileCol + nCol0 + nt * 8 + clo];
        clab[nt * 2 + 1] = g_labels[tileCol + nCol0 + nt * 8 + clo + 1];
    }

    // pass 1: row orientation directly from registers; stage e=exp(40v) in SMEM
#pragma unroll
    for (int mt = 0; mt < 4; mt++) {
#pragma unroll
        for (int h = 0; h < 2; h++) {
            int r = mRow0 + mt * 16 + rhi + h * 8;
            int R = tileRow + r;
            int rlab = g_labels[R];
            float emax = 0.0f, ns = 0.0f;
            int nn = 0;
#pragma unroll
            for (int nt = 0; nt < 8; nt++) {
#pragma unroll
                for (int q2 = 0; q2 < 2; q2++) {
                    float v = acc[mt][nt][h * 2 + q2];
                    float e = __expf(SCALE_NEG * v);
                    int cc = nCol0 + nt * 8 + clo + q2;
                    C[r * 128 + (cc ^ (r & 31))] = e;
                    if (clab[nt * 2 + q2] != rlab) {
                        nn++;
                        ns += e;
                        emax = fmaxf(emax, e);
                    } else if (v < (1.0f - EPS_C)) {
                        int slot = atomicAdd(&g_poscnt[R], 1);
                        if (slot < POS_SLOTS)
                            g_posval[(size_t)R * POS_SLOTS + slot] = v;
                    }
                }
            }
            // reduce across the 4 lanes sharing this row (lid&3 = 0..3)
            ns   += __shfl_xor_sync(0xFFFFFFFFu, ns, 1);
            nn   += __shfl_xor_sync(0xFFFFFFFFu, nn, 1);
            emax  = fmaxf(emax, __shfl_xor_sync(0xFFFFFFFFu, emax, 1));
            ns   += __shfl_xor_sync(0xFFFFFFFFu, ns, 2);
            nn   += __shfl_xor_sync(0xFFFFFFFFu, nn, 2);
            emax  = fmaxf(emax, __shfl_xor_sync(0xFFFFFFFFu, emax, 2));
            if ((lid & 3) == 0) {
                atomicAdd(&g_negsum[R], ns);
                atomicAdd(&g_nneg[R], nn);
                atomicMax(reinterpret_cast<int*>(&g_maxE[R]), __float_as_int(emax));
            }
        }
    }
    __syncthreads();

    // pass 2: mirror orientation from SMEM e-tile (off-diagonal tiles only).
    // Thread t owns tile-local column t  ->  global mirror-row tileCol + t.
    if (!diag) {
        const int t = tid;
        const int Cg = tileCol + t;
        const int tl = g_labels[Cg];
        float emax = 0.0f, ns = 0.0f;
        int nn = 0;
#pragma unroll 4
        for (int r = 0; r < 128; r++) {
            float e = C[r * 128 + (t ^ (r & 31))];
            int rl2 = g_labels[tileRow + r];       // uniform per iter -> broadcast
            if (rl2 != tl) {
                nn++;
                ns += e;
                emax = fmaxf(emax, e);
            } else {
                float v = __logf(e) * (1.0f / SCALE_NEG);
                if (v < (1.0f - EPS_C)) {
                    int slot = atomicAdd(&g_poscnt[Cg], 1);
                    if (slot < POS_SLOTS)
                        g_posval[(size_t)Cg * POS_SLOTS + slot] = v;
                }
            }
        }
        atomicAdd(&g_negsum[Cg], ns);
        atomicAdd(&g_nneg[Cg], nn);
        atomicMax(reinterpret_cast<int*>(&g_maxE[Cg]), __float_as_int(emax));
    }
}

// -------------------- kernel 3: per-row finalize --------------------
__global__ void __launch_bounds__(256) finalize_kernel() {
    int r = blockIdx.x * 256 + threadIdx.x;
    float per = 0.0f;
    int n_neg = g_nneg[r];
    int cand = g_poscnt[r];
    if (cand > POS_SLOTS) cand = POS_SLOTS;
    if (n_neg >= 1 && cand > 0) {
        float neg_sum = g_negsum[r];
        float maxneg = __logf(g_maxE[r]) * (1.0f / SCALE_NEG);
        float ps = 0.0f;
        int np = 0;
        const float* pv = g_posval + (size_t)r * POS_SLOTS;
        for (int k = 0; k < cand; k++) {
            float v = pv[k];
            if ((v - MARGIN) < maxneg) {
                np++;
                ps += __expf(-SCALE_POS * v);
            }
        }
        if (np >= 1) {
            float pos_loss = (1.0f / SCALE_POS) *
                __logf((ps + __expf(-SCALE_POS * THRESH1)) / (float)(np + 1));
            float neg_loss = (1.0f / SCALE_NEG) *
                __logf((neg_sum + __expf(SCALE_NEG * THRESH2)) / (float)(n_neg + 1));
            per = __logf(5.33f + __expf(pos_loss + neg_loss));
        }
    }
    g_row[r] = per;
}

// -------------------- kernel 4: final reduce (float4 + shuffle) --------------------
__global__ void __launch_bounds__(256) final_reduce_kernel(float* __restrict__ out) {
    __shared__ float wsum[8];
    int tid = threadIdx.x;
    int lid = tid & 31, wrp = tid >> 5;
    const float4* r4 = reinterpret_cast<const float4*>(g_row);
    float s = 0.0f;
#pragma unroll
    for (int it = 0; it < 4; it++) {
        float4 v = r4[it * 256 + tid];
        s += (v.x + v.y) + (v.z + v.w);
    }
#pragma unroll
    for (int o = 16; o > 0; o >>= 1) s += __shfl_xor_sync(0xFFFFFFFFu, s, o);
    if (lid == 0) wsum[wrp] = s;
    __syncthreads();
    if (tid == 0) {
        float t = 0.0f;
#pragma unroll
        for (int w = 0; w < 8; w++) t += wsum[w];
        out[0] = t * (1.0f / (float)NB);
    }
}

// ---------------------------------------------------------------------------
extern "C" void kernel_launch(void* const* d_in, const int* in_sizes, int n_in,
                              void* d_out, int out_size) {
    const float* feats = (const float*)d_in[0];
    const int* labels = (const int*)d_in[1];
    float* out = (float*)d_out;

    cudaFuncSetAttribute(gemm_mma_kernel,
                         cudaFuncAttributeMaxDynamicSharedMemorySize, DYNSMEM);

    labels_kernel<<<1, 256>>>(labels);
    convert_kernel<<<2048, 512>>>(feats);            // 4M elems, 1 float4/thread
    gemm_mma_kernel<<<dim3(32, 32), 128, DYNSMEM>>>();
    finalize_kernel<<<16, 256>>>();
    final_reduce_kernel<<<1, 256>>>(out);
}

// round 11
// speedup vs baseline: 1.4438x; 1.4438x over previous
#include <cuda_runtime.h>
#include <cuda_bf16.h>
#include <math.h>
#include <stdint.h>

// Problem constants (fixed by the reference: B=4096, D=1024, N_CLASSES=64)
#define NB 4096
#define ND 1024

#define MARGIN    0.09f
#define SCALE_POS 2.0f
#define SCALE_NEG 40.0f
#define EPS_C     1e-5f
#define THRESH1   0.501f
#define THRESH2   0.531f

// -------------------- device scratch (no runtime allocation) --------------------
__device__ float g_sim[(size_t)NB * NB];   // 64 MB similarity matrix
__device__ float g_t32[(size_t)NB * ND];   // 16 MB tf32-rounded feats
__device__ int   g_labels[NB];
__device__ float g_row[NB];

// -------------------- PTX helpers (plain sm_80 features only) --------------------
__device__ __forceinline__ uint32_t smem_u32(const void* p) {
    uint32_t a;
    asm("{ .reg .u64 t; cvta.to.shared.u64 t, %1; cvt.u32.u64 %0, t; }" : "=r"(a) : "l"(p));
    return a;
}
__device__ __forceinline__ void cp16(uint32_t s, const void* g) {
    asm volatile("cp.async.cg.shared.global [%0], [%1], 16;" :: "r"(s), "l"(g));
}
#define CP_COMMIT() asm volatile("cp.async.commit_group;" ::: "memory")
#define CP_WAIT2()  asm volatile("cp.async.wait_group 2;" ::: "memory")

__device__ __forceinline__ void ldsm4(uint32_t* r, uint32_t addr) {
    asm volatile("ldmatrix.sync.aligned.m8n8.x4.shared.b16 {%0,%1,%2,%3}, [%4];"
                 : "=r"(r[0]), "=r"(r[1]), "=r"(r[2]), "=r"(r[3]) : "r"(addr));
}
// m16n8k8 tf32: A = 4 regs, B = 2 regs, fp32 accum
__device__ __forceinline__ void mma_tf32(float* d, const uint32_t* a,
                                         uint32_t b0, uint32_t b1) {
    asm volatile(
        "mma.sync.aligned.m16n8k8.row.col.f32.tf32.tf32.f32 "
        "{%0,%1,%2,%3}, {%4,%5,%6,%7}, {%8,%9}, {%0,%1,%2,%3};"
        : "+f"(d[0]), "+f"(d[1]), "+f"(d[2]), "+f"(d[3])
        : "r"(a[0]), "r"(a[1]), "r"(a[2]), "r"(a[3]), "r"(b0), "r"(b1));
}
__device__ __forceinline__ uint32_t to_tf32(float x) {
    uint32_t o;
    asm("cvt.rna.tf32.f32 %0, %1;" : "=r"(o) : "f"(x));
    return o;
}

// -------------------- kernel 0: labels (int64/int32 auto-detect) --------------------
__global__ void __launch_bounds__(256) labels_kernel(const int* __restrict__ lab) {
    __shared__ int sred[256];
    __shared__ int s_is64;
    int tid = threadIdx.x;
    int acc = 0;
    for (int i = tid; i < 2048; i += 256) acc |= lab[2 * i + 1];
    sred[tid] = acc;
    __syncthreads();
    for (int o = 128; o > 0; o >>= 1) {
        if (tid < o) sred[tid] |= sred[tid + o];
        __syncthreads();
    }
    if (tid == 0) s_is64 = (sred[0] == 0) ? 1 : 0;
    __syncthreads();
    int is64 = s_is64;
    for (int i = tid; i < NB; i += 256)
        g_labels[i] = is64 ? lab[2 * i] : lab[i];
}

// -------------------- kernel 1: f32 -> tf32 (round-to-nearest) --------------------
__global__ void __launch_bounds__(512) convert_kernel(const float* __restrict__ F) {
    size_t i = (size_t)blockIdx.x * 512 + threadIdx.x;   // one float4 per thread
    float4 v = reinterpret_cast<const float4*>(F)[i];
    uint4 o;
    o.x = to_tf32(v.x);
    o.y = to_tf32(v.y);
    o.z = to_tf32(v.z);
    o.w = to_tf32(v.w);
    reinterpret_cast<uint4*>(g_t32)[i] = o;
}

// -------------------- kernel 2: mma.sync tf32 symmetric GEMM --------------------
// 256x128 CTA tiles (halved L2 traffic per output), triangular cover:
// row band by (256 rows) x col tile bx (128 cols), bx >= 2*by -> 272 CTAs.
// 8 warps x (64x64), BK=32 f32, 3-stage cp.async pipeline.
// Near-diagonal duplicate elements are computed/stored by two CTAs with
// bit-identical values (same K-order FMA) -> benign.
#define STAGE_BYTES 49152          // A 32KB (256x128B) + B 16KB (128x128B)
#define NCHUNK 32
#define NTILE 272                  // sum_{by=0..15} (32 - 2*by)
#define DYNSMEM (3 * STAGE_BYTES)  // 144 KB (epilogue reuses 128 KB)

__device__ __forceinline__ void load_chunk(int c, uint32_t stage,
                                           int rowA, int rowB, int tid) {
    const uint8_t* base = reinterpret_cast<const uint8_t*>(g_t32);
    size_t k0 = (size_t)c * 128;     // byte offset within 4096B row
    uint32_t sB = stage + 32768;
    // A: 256 rows -> 2048 16B units, 8 per thread
#pragma unroll
    for (int j = 0; j < 8; j++) {
        int u = (j << 8) + tid;
        int r = u >> 3;
        int ch = u & 7;
        uint32_t off = (uint32_t)((r << 7) + (ch << 4));
        uint32_t sw = off ^ ((off >> 3) & 0x70);
        cp16(stage + sw, base + (size_t)(rowA + r) * 4096 + k0 + (ch << 4));
    }
    // B: 128 rows -> 1024 16B units, 4 per thread
#pragma unroll
    for (int j = 0; j < 4; j++) {
        int u = (j << 8) + tid;
        int r = u >> 3;
        int ch = u & 7;
        uint32_t off = (uint32_t)((r << 7) + (ch << 4));
        uint32_t sw = off ^ ((off >> 3) & 0x70);
        cp16(sB + sw, base + (size_t)(rowB + r) * 4096 + k0 + (ch << 4));
    }
}

__global__ void __launch_bounds__(256, 1) gemm_mma_kernel() {
    extern __shared__ char dsm[];
    // decode tile id -> (by, bx): band by has tiles bx in [2*by, 31]
    const int i = blockIdx.x;
    int by = 0;
    while ((by + 1) * (33 - (by + 1)) <= i) by++;    // cum(by) = by*(33-by)
    const int bx = 2 * by + (i - by * (33 - by));

    const int tid = threadIdx.x;
    const int lid = tid & 31;
    const int wid = tid >> 5;            // 0..7
    const int tileRow = by * 256;
    const int tileCol = bx * 128;

    uint32_t SB = (smem_u32(dsm) + 127u) & ~127u;

    // warp tile: 64 (M) x 64 (N); warp grid 4 x 2
    const int mRow0 = (wid >> 1) * 64;   // 0,64,128,192
    const int nCol0 = (wid & 1) * 64;    // 0,64

    // ldmatrix lane addressing (b16-view of f32 tiles)
    const int aRow  = lid & 15;
    const int aKoff = ((lid >> 4) & 1) * 16;         // bytes
    const int bRow  = (lid & 7) + ((lid >> 4) << 3);
    const int bKoff = ((lid >> 3) & 1) * 16;         // bytes

    float acc[4][8][4];
#pragma unroll
    for (int mt = 0; mt < 4; mt++)
#pragma unroll
        for (int nt = 0; nt < 8; nt++)
#pragma unroll
            for (int q = 0; q < 4; q++) acc[mt][nt][q] = 0.0f;

    load_chunk(0, SB + 0 * STAGE_BYTES, tileRow, tileCol, tid); CP_COMMIT();
    load_chunk(1, SB + 1 * STAGE_BYTES, tileRow, tileCol, tid); CP_COMMIT();

    for (int c = 0; c < NCHUNK; c++) {
        if (c + 2 < NCHUNK)
            load_chunk(c + 2, SB + ((c + 2) % 3) * STAGE_BYTES, tileRow, tileCol, tid);
        CP_COMMIT();
        CP_WAIT2();
        __syncthreads();

        uint32_t sa = SB + (c % 3) * STAGE_BYTES;
        uint32_t sbm = sa + 32768;
#pragma unroll
        for (int kk = 0; kk < 4; kk++) {             // 4 x k8 within BK=32 f32
            uint32_t afrag[4][4];
#pragma unroll
            for (int mt = 0; mt < 4; mt++) {
                uint32_t off = (uint32_t)((mRow0 + mt * 16 + aRow) * 128 +
                                          aKoff + kk * 32);
                ldsm4(afrag[mt], sa + (off ^ ((off >> 3) & 0x70)));
            }
            uint32_t bfrag[4][4];                     // each g: n16 (two n8 frags)
#pragma unroll
            for (int g = 0; g < 4; g++) {
                uint32_t off = (uint32_t)((nCol0 + g * 16 + bRow) * 128 +
                                          bKoff + kk * 32);
                ldsm4(bfrag[g], sbm + (off ^ ((off >> 3) & 0x70)));
            }
#pragma unroll
            for (int mt = 0; mt < 4; mt++)
#pragma unroll
                for (int g = 0; g < 4; g++) {
                    mma_tf32(acc[mt][g * 2],     afrag[mt], bfrag[g][0], bfrag[g][1]);
                    mma_tf32(acc[mt][g * 2 + 1], afrag[mt], bfrag[g][2], bfrag[g][3]);
                }
        }
        __syncthreads();
    }

    // ---- epilogue: fragments -> XOR-swizzled SMEM (256x128) -> stores ----
    float* C = reinterpret_cast<float*>(dsm);
#pragma unroll
    for (int mt = 0; mt < 4; mt++) {
        int r0 = mRow0 + mt * 16 + (lid >> 2);
#pragma unroll
        for (int nt = 0; nt < 8; nt++) {
            int cc = nCol0 + nt * 8 + (lid & 3) * 2;
            C[r0 * 128 + (cc ^ (r0 & 31))]       = acc[mt][nt][0];
            C[r0 * 128 + ((cc + 1) ^ (r0 & 31))] = acc[mt][nt][1];
            int r1 = r0 + 8;
            C[r1 * 128 + (cc ^ (r1 & 31))]       = acc[mt][nt][2];
            C[r1 * 128 + ((cc + 1) ^ (r1 & 31))] = acc[mt][nt][3];
        }
    }
    __syncthreads();

    // normal store: 256 rows x 128 cols
#pragma unroll 4
    for (int it = 0; it < 128; it++) {
        int idx = it * 256 + tid;
        int r = idx >> 7, cc = idx & 127;
        g_sim[(size_t)(tileRow + r) * NB + tileCol + cc] = C[r * 128 + (cc ^ (r & 31))];
    }
    // mirror store: 128 rows x 256 cols (duplicate elems bitwise-identical)
#pragma unroll 4
    for (int it = 0; it < 128; it++) {
        int idx = it * 256 + tid;
        int j = idx >> 8;            // 0..127  (mirror row offset)
        int ii = idx & 255;          // 0..255  (mirror col offset)
        g_sim[(size_t)(tileCol + j) * NB + tileRow + ii] = C[ii * 128 + (j ^ (ii & 31))];
    }
}

// -------------------- kernel 3: per-row reductions (register-resident) --------------------
__global__ void __launch_bounds__(256) row_kernel() {
    const int row = blockIdx.x;
    const int tid = threadIdx.x;
    const int lid = tid & 31;
    const int wrp = tid >> 5;

    __shared__ float wmx[8], wns[8], wps[8];
    __shared__ int   wnn[8], wnp[8];
    __shared__ float s_maxneg, s_negsum;
    __shared__ int   s_nneg;

    const float4* srow = reinterpret_cast<const float4*>(g_sim + (size_t)row * NB);
    const int4*   lab4 = reinterpret_cast<const int4*>(g_labels);
    const int rl = g_labels[row];

    float s[16];
    uint32_t m_pc = 0;   // bit q: label == rl && s < 1-eps (pos candidate)

    float mx = -INFINITY, ns = 0.0f;
    int nn = 0;

#pragma unroll
    for (int it = 0; it < 4; it++) {
        float4 v = srow[it * 256 + tid];
        int4 L = lab4[it * 256 + tid];
        s[it * 4 + 0] = v.x; s[it * 4 + 1] = v.y;
        s[it * 4 + 2] = v.z; s[it * 4 + 3] = v.w;
        int l[4] = {L.x, L.y, L.z, L.w};
#pragma unroll
        for (int q = 0; q < 4; q++) {
            float sv = s[it * 4 + q];
            bool neq = (l[q] != rl);
            if (neq) {
                nn++;
                ns += __expf(SCALE_NEG * sv);
                mx = fmaxf(mx, sv);
            } else if (sv < (1.0f - EPS_C)) {
                m_pc |= (1u << (it * 4 + q));
            }
        }
    }

#pragma unroll
    for (int o = 16; o > 0; o >>= 1) {
        mx = fmaxf(mx, __shfl_xor_sync(0xFFFFFFFFu, mx, o));
        ns += __shfl_xor_sync(0xFFFFFFFFu, ns, o);
        nn += __shfl_xor_sync(0xFFFFFFFFu, nn, o);
    }
    if (lid == 0) { wmx[wrp] = mx; wns[wrp] = ns; wnn[wrp] = nn; }
    __syncthreads();
    if (wrp == 0) {
        float m2 = (lid < 8) ? wmx[lid] : -INFINITY;
        float n2 = (lid < 8) ? wns[lid] : 0.0f;
        int   c2 = (lid < 8) ? wnn[lid] : 0;
#pragma unroll
        for (int o = 4; o > 0; o >>= 1) {
            m2 = fmaxf(m2, __shfl_xor_sync(0xFFFFFFFFu, m2, o));
            n2 += __shfl_xor_sync(0xFFFFFFFFu, n2, o);
            c2 += __shfl_xor_sync(0xFFFFFFFFu, c2, o);
        }
        if (lid == 0) { s_maxneg = m2; s_negsum = n2; s_nneg = c2; }
    }
    __syncthreads();

    const float maxneg = s_maxneg;

    float ps = 0.0f;
    int np = 0;
    uint32_t m = m_pc;
#pragma unroll
    for (int q = 0; q < 16; q++) {
        if (m & (1u << q)) {
            float sv = s[q];
            if ((sv - MARGIN) < maxneg) {
                np++;
                ps += __expf(-SCALE_POS * sv);
            }
        }
    }
#pragma unroll
    for (int o = 16; o > 0; o >>= 1) {
        ps += __shfl_xor_sync(0xFFFFFFFFu, ps, o);
        np += __shfl_xor_sync(0xFFFFFFFFu, np, o);
    }
    if (lid == 0) { wps[wrp] = ps; wnp[wrp] = np; }
    __syncthreads();
    if (tid == 0) {
        float pos_sum = 0.0f;
        int n_pos = 0;
#pragma unroll
        for (int w = 0; w < 8; w++) { pos_sum += wps[w]; n_pos += wnp[w]; }
        float neg_sum = s_negsum;
        int n_neg = s_nneg;
        float pos_loss = (1.0f / SCALE_POS) *
            __logf((pos_sum + __expf(-SCALE_POS * THRESH1)) / (float)(n_pos + 1));
        float neg_loss = (1.0f / SCALE_NEG) *
            __logf((neg_sum + __expf(SCALE_NEG * THRESH2)) / (float)(n_neg + 1));
        float per_row = __logf(5.33f + __expf(pos_loss + neg_loss));
        g_row[row] = (n_neg >= 1 && n_pos >= 1) ? per_row : 0.0f;
    }
}

// -------------------- kernel 4: final reduce (float4 + shuffle) --------------------
__global__ void __launch_bounds__(256) final_reduce_kernel(float* __restrict__ out) {
    __shared__ float wsum[8];
    int tid = threadIdx.x;
    int lid = tid & 31, wrp = tid >> 5;
    const float4* r4 = reinterpret_cast<const float4*>(g_row);
    float s = 0.0f;
#pragma unroll
    for (int it = 0; it < 4; it++) {
        float4 v = r4[it * 256 + tid];
        s += (v.x + v.y) + (v.z + v.w);
    }
#pragma unroll
    for (int o = 16; o > 0; o >>= 1) s += __shfl_xor_sync(0xFFFFFFFFu, s, o);
    if (lid == 0) wsum[wrp] = s;
    __syncthreads();
    if (tid == 0) {
        float t = 0.0f;
#pragma unroll
        for (int w = 0; w < 8; w++) t += wsum[w];
        out[0] = t * (1.0f / (float)NB);
    }
}

// ---------------------------------------------------------------------------
extern "C" void kernel_launch(void* const* d_in, const int* in_sizes, int n_in,
                              void* d_out, int out_size) {
    const float* feats = (const float*)d_in[0];
    const int* labels = (const int*)d_in[1];
    float* out = (float*)d_out;

    cudaFuncSetAttribute(gemm_mma_kernel,
                         cudaFuncAttributeMaxDynamicSharedMemorySize, DYNSMEM);

    labels_kernel<<<1, 256>>>(labels);
    convert_kernel<<<2048, 512>>>(feats);            // 4M elems, 1 float4/thread
    gemm_mma_kernel<<<NTILE, 256, DYNSMEM>>>();
    row_kernel<<<NB, 256>>>();
    final_reduce_kernel<<<1, 256>>>(out);
}

// round 12
// speedup vs baseline: 1.7062x; 1.1817x over previous
#include <cuda_runtime.h>
#include <cuda_fp16.h>
#include <math.h>
#include <stdint.h>

// Problem constants (fixed by the reference: B=4096, D=1024, N_CLASSES=64)
#define NB 4096
#define ND 1024

#define MARGIN    0.09f
#define SCALE_POS 2.0f
#define SCALE_NEG 40.0f
#define EPS_C     1e-5f
#define THRESH1   0.501f
#define THRESH2   0.531f

// -------------------- device scratch (no runtime allocation) --------------------
__device__ __half g_sim16[(size_t)NB * NB];  // 32 MB similarity matrix (fp16)
__device__ float  g_t32[(size_t)NB * ND];    // 16 MB tf32-rounded feats
__device__ int    g_labels[NB];
__device__ float  g_row[NB];

// -------------------- PTX helpers (plain sm_80 features only) --------------------
__device__ __forceinline__ uint32_t smem_u32(const void* p) {
    uint32_t a;
    asm("{ .reg .u64 t; cvta.to.shared.u64 t, %1; cvt.u32.u64 %0, t; }" : "=r"(a) : "l"(p));
    return a;
}
__device__ __forceinline__ void cp16(uint32_t s, const void* g) {
    asm volatile("cp.async.cg.shared.global [%0], [%1], 16;" :: "r"(s), "l"(g));
}
#define CP_COMMIT() asm volatile("cp.async.commit_group;" ::: "memory")
#define CP_WAIT2()  asm volatile("cp.async.wait_group 2;" ::: "memory")

__device__ __forceinline__ void ldsm4(uint32_t* r, uint32_t addr) {
    asm volatile("ldmatrix.sync.aligned.m8n8.x4.shared.b16 {%0,%1,%2,%3}, [%4];"
                 : "=r"(r[0]), "=r"(r[1]), "=r"(r[2]), "=r"(r[3]) : "r"(addr));
}
// m16n8k8 tf32: A = 4 regs, B = 2 regs, fp32 accum
__device__ __forceinline__ void mma_tf32(float* d, const uint32_t* a,
                                         uint32_t b0, uint32_t b1) {
    asm volatile(
        "mma.sync.aligned.m16n8k8.row.col.f32.tf32.tf32.f32 "
        "{%0,%1,%2,%3}, {%4,%5,%6,%7}, {%8,%9}, {%0,%1,%2,%3};"
        : "+f"(d[0]), "+f"(d[1]), "+f"(d[2]), "+f"(d[3])
        : "r"(a[0]), "r"(a[1]), "r"(a[2]), "r"(a[3]), "r"(b0), "r"(b1));
}
__device__ __forceinline__ uint32_t to_tf32(float x) {
    uint32_t o;
    asm("cvt.rna.tf32.f32 %0, %1;" : "=r"(o) : "f"(x));
    return o;
}

// -------------------- kernel 0: labels (int64/int32 auto-detect) --------------------
__global__ void __launch_bounds__(256) labels_kernel(const int* __restrict__ lab) {
    __shared__ int sred[256];
    __shared__ int s_is64;
    int tid = threadIdx.x;
    int acc = 0;
    for (int i = tid; i < 2048; i += 256) acc |= lab[2 * i + 1];
    sred[tid] = acc;
    __syncthreads();
    for (int o = 128; o > 0; o >>= 1) {
        if (tid < o) sred[tid] |= sred[tid + o];
        __syncthreads();
    }
    if (tid == 0) s_is64 = (sred[0] == 0) ? 1 : 0;
    __syncthreads();
    int is64 = s_is64;
    for (int i = tid; i < NB; i += 256)
        g_labels[i] = is64 ? lab[2 * i] : lab[i];
}

// -------------------- kernel 1: f32 -> tf32 (round-to-nearest) --------------------
__global__ void __launch_bounds__(512) convert_kernel(const float* __restrict__ F) {
    size_t i = (size_t)blockIdx.x * 512 + threadIdx.x;   // one float4 per thread
    float4 v = reinterpret_cast<const float4*>(F)[i];
    uint4 o;
    o.x = to_tf32(v.x);
    o.y = to_tf32(v.y);
    o.z = to_tf32(v.z);
    o.w = to_tf32(v.w);
    reinterpret_cast<uint4*>(g_t32)[i] = o;
}

// -------------------- kernel 2: mma.sync tf32 symmetric GEMM (R8-proven) ------------
// sim = T * T^T single pass (tf32, K=1024). 128x128 tiles, upper triangle + mirror.
// 4 warps x (64x64); BK=32 f32; 3-stage cp.async pipeline; fp16 output stores.
#define STAGE_BYTES 32768          // A 16KB + B 16KB
#define NCHUNK 32
#define DYNSMEM (3 * STAGE_BYTES)  // 96 KB (epilogue reuses 64 KB of it)

__device__ __forceinline__ void load_chunk(int c, uint32_t stage,
                                           int rowA, int rowB, int tid) {
    const uint8_t* base = reinterpret_cast<const uint8_t*>(g_t32);
    size_t k0 = (size_t)c * 128;     // byte offset within 4096B row
    uint32_t sB = stage + 16384;
#pragma unroll
    for (int j = 0; j < 8; j++) {
        int u = (j << 7) + tid;          // 0..1023 16B units per operand
        int r = u >> 3;                  // row 0..127
        int ch = u & 7;                  // 16B chunk within 128B row
        uint32_t off = (uint32_t)((r << 7) + (ch << 4));
        uint32_t sw = off ^ ((off >> 3) & 0x70);
        cp16(stage + sw, base + (size_t)(rowA + r) * 4096 + k0 + (ch << 4));
        cp16(sB + sw,    base + (size_t)(rowB + r) * 4096 + k0 + (ch << 4));
    }
}

__global__ void __launch_bounds__(128, 2) gemm_mma_kernel() {
    extern __shared__ char dsm[];
    if ((int)blockIdx.x < (int)blockIdx.y) return;   // upper triangle only
    const int tid = threadIdx.x;
    const int lid = tid & 31;
    const int wid = tid >> 5;            // 0..3
    const int tileRow = blockIdx.y * 128;
    const int tileCol = blockIdx.x * 128;

    uint32_t SB = (smem_u32(dsm) + 127u) & ~127u;

    // warp tile: 64 (M) x 64 (N); warp grid 2 x 2
    const int mRow0 = (wid >> 1) * 64;
    const int nCol0 = (wid & 1) * 64;

    // ldmatrix lane addressing (b16-view of f32 tiles)
    const int aRow  = lid & 15;
    const int aKoff = ((lid >> 4) & 1) * 16;         // bytes
    const int bRow  = (lid & 7) + ((lid >> 4) << 3);
    const int bKoff = ((lid >> 3) & 1) * 16;         // bytes

    float acc[4][8][4];
#pragma unroll
    for (int mt = 0; mt < 4; mt++)
#pragma unroll
        for (int nt = 0; nt < 8; nt++)
#pragma unroll
            for (int q = 0; q < 4; q++) acc[mt][nt][q] = 0.0f;

    load_chunk(0, SB + 0 * STAGE_BYTES, tileRow, tileCol, tid); CP_COMMIT();
    load_chunk(1, SB + 1 * STAGE_BYTES, tileRow, tileCol, tid); CP_COMMIT();

    for (int c = 0; c < NCHUNK; c++) {
        if (c + 2 < NCHUNK)
            load_chunk(c + 2, SB + ((c + 2) % 3) * STAGE_BYTES, tileRow, tileCol, tid);
        CP_COMMIT();
        CP_WAIT2();
        __syncthreads();

        uint32_t sa = SB + (c % 3) * STAGE_BYTES;
        uint32_t sbm = sa + 16384;
#pragma unroll
        for (int kk = 0; kk < 4; kk++) {             // 4 x k8 within BK=32 f32
            uint32_t afrag[4][4];
#pragma unroll
            for (int mt = 0; mt < 4; mt++) {
                uint32_t off = (uint32_t)((mRow0 + mt * 16 + aRow) * 128 +
                                          aKoff + kk * 32);
                ldsm4(afrag[mt], sa + (off ^ ((off >> 3) & 0x70)));
            }
            uint32_t bfrag[4][4];                     // each g: n16 (two n8 frags)
#pragma unroll
            for (int g = 0; g < 4; g++) {
                uint32_t off = (uint32_t)((nCol0 + g * 16 + bRow) * 128 +
                                          bKoff + kk * 32);
                ldsm4(bfrag[g], sbm + (off ^ ((off >> 3) & 0x70)));
            }
#pragma unroll
            for (int mt = 0; mt < 4; mt++)
#pragma unroll
                for (int g = 0; g < 4; g++) {
                    mma_tf32(acc[mt][g * 2],     afrag[mt], bfrag[g][0], bfrag[g][1]);
                    mma_tf32(acc[mt][g * 2 + 1], afrag[mt], bfrag[g][2], bfrag[g][3]);
                }
        }
        __syncthreads();
    }

    // ---- epilogue: fragments -> XOR-swizzled SMEM -> fp16 normal + mirror stores ----
    float* C = reinterpret_cast<float*>(dsm);
#pragma unroll
    for (int mt = 0; mt < 4; mt++) {
        int r0 = mRow0 + mt * 16 + (lid >> 2);
#pragma unroll
        for (int nt = 0; nt < 8; nt++) {
            int cc = nCol0 + nt * 8 + (lid & 3) * 2;
            C[r0 * 128 + (cc ^ (r0 & 31))]       = acc[mt][nt][0];
            C[r0 * 128 + ((cc + 1) ^ (r0 & 31))] = acc[mt][nt][1];
            int r1 = r0 + 8;
            C[r1 * 128 + (cc ^ (r1 & 31))]       = acc[mt][nt][2];
            C[r1 * 128 + ((cc + 1) ^ (r1 & 31))] = acc[mt][nt][3];
        }
    }
    __syncthreads();

    // normal store: 8192 half2 units, 64 per thread
#pragma unroll 4
    for (int it = 0; it < 64; it++) {
        int idx = it * 128 + tid;
        int r = idx >> 6;                // 0..127
        int c2 = (idx & 63) * 2;         // even col
        float v0 = C[r * 128 + (c2 ^ (r & 31))];
        float v1 = C[r * 128 + ((c2 + 1) ^ (r & 31))];
        *reinterpret_cast<__half2*>(
            &g_sim16[(size_t)(tileRow + r) * NB + tileCol + c2]) =
            __floats2half2_rn(v0, v1);
    }
    if (blockIdx.x != blockIdx.y) {
#pragma unroll 4
        for (int it = 0; it < 64; it++) {
            int idx = it * 128 + tid;
            int j = idx >> 6;            // mirror row offset 0..127
            int i2 = (idx & 63) * 2;     // even mirror col
            float v0 = C[i2 * 128 + (j ^ (i2 & 31))];
            float v1 = C[(i2 + 1) * 128 + (j ^ ((i2 + 1) & 31))];
            *reinterpret_cast<__half2*>(
                &g_sim16[(size_t)(tileCol + j) * NB + tileRow + i2]) =
                __floats2half2_rn(v0, v1);
        }
    }
}

// -------------------- kernel 3: per-row reductions (fp16 sim, register-resident) ----
__global__ void __launch_bounds__(256) row_kernel() {
    const int row = blockIdx.x;
    const int tid = threadIdx.x;
    const int lid = tid & 31;
    const int wrp = tid >> 5;

    __shared__ float wmx[8], wns[8], wps[8];
    __shared__ int   wnn[8], wnp[8];
    __shared__ float s_maxneg, s_negsum;
    __shared__ int   s_nneg;

    const uint4* srow = reinterpret_cast<const uint4*>(g_sim16 + (size_t)row * NB);
    const int4*  lab4 = reinterpret_cast<const int4*>(g_labels);
    const int rl = g_labels[row];

    float s[16];
    uint32_t m_pc = 0;   // bit q: label == rl && s < 1-eps (pos candidate)

    float mx = -INFINITY, ns = 0.0f;
    int nn = 0;

#pragma unroll
    for (int it = 0; it < 2; it++) {
        uint4 raw = srow[it * 256 + tid];            // 8 halves
        int4 L0 = lab4[(it * 256 + tid) * 2];
        int4 L1 = lab4[(it * 256 + tid) * 2 + 1];
        float2 f0 = __half22float2(*reinterpret_cast<const __half2*>(&raw.x));
        float2 f1 = __half22float2(*reinterpret_cast<const __half2*>(&raw.y));
        float2 f2 = __half22float2(*reinterpret_cast<const __half2*>(&raw.z));
        float2 f3 = __half22float2(*reinterpret_cast<const __half2*>(&raw.w));
        float sv[8] = {f0.x, f0.y, f1.x, f1.y, f2.x, f2.y, f3.x, f3.y};
        int lv[8] = {L0.x, L0.y, L0.z, L0.w, L1.x, L1.y, L1.z, L1.w};
#pragma unroll
        for (int q = 0; q < 8; q++) {
            s[it * 8 + q] = sv[q];
            if (lv[q] != rl) {
                nn++;
                ns += __expf(SCALE_NEG * sv[q]);
                mx = fmaxf(mx, sv[q]);
            } else if (sv[q] < (1.0f - EPS_C)) {
                m_pc |= (1u << (it * 8 + q));
            }
        }
    }

#pragma unroll
    for (int o = 16; o > 0; o >>= 1) {
        mx = fmaxf(mx, __shfl_xor_sync(0xFFFFFFFFu, mx, o));
        ns += __shfl_xor_sync(0xFFFFFFFFu, ns, o);
        nn += __shfl_xor_sync(0xFFFFFFFFu, nn, o);
    }
    if (lid == 0) { wmx[wrp] = mx; wns[wrp] = ns; wnn[wrp] = nn; }
    __syncthreads();
    if (wrp == 0) {
        float m2 = (lid < 8) ? wmx[lid] : -INFINITY;
        float n2 = (lid < 8) ? wns[lid] : 0.0f;
        int   c2 = (lid < 8) ? wnn[lid] : 0;
#pragma unroll
        for (int o = 4; o > 0; o >>= 1) {
            m2 = fmaxf(m2, __shfl_xor_sync(0xFFFFFFFFu, m2, o));
            n2 += __shfl_xor_sync(0xFFFFFFFFu, n2, o);
            c2 += __shfl_xor_sync(0xFFFFFFFFu, c2, o);
        }
        if (lid == 0) { s_maxneg = m2; s_negsum = n2; s_nneg = c2; }
    }
    __syncthreads();

    const float maxneg = s_maxneg;

    float ps = 0.0f;
    int np = 0;
    uint32_t m = m_pc;
#pragma unroll
    for (int q = 0; q < 16; q++) {
        if (m & (1u << q)) {
            float sv = s[q];
            if ((sv - MARGIN) < maxneg) {
                np++;
                ps += __expf(-SCALE_POS * sv);
            }
        }
    }
#pragma unroll
    for (int o = 16; o > 0; o >>= 1) {
        ps += __shfl_xor_sync(0xFFFFFFFFu, ps, o);
        np += __shfl_xor_sync(0xFFFFFFFFu, np, o);
    }
    if (lid == 0) { wps[wrp] = ps; wnp[wrp] = np; }
    __syncthreads();
    if (tid == 0) {
        float pos_sum = 0.0f;
        int n_pos = 0;
#pragma unroll
        for (int w = 0; w < 8; w++) { pos_sum += wps[w]; n_pos += wnp[w]; }
        float neg_sum = s_negsum;
        int n_neg = s_nneg;
        float pos_loss = (1.0f / SCALE_POS) *
            __logf((pos_sum + __expf(-SCALE_POS * THRESH1)) / (float)(n_pos + 1));
        float neg_loss = (1.0f / SCALE_NEG) *
            __logf((neg_sum + __expf(SCALE_NEG * THRESH2)) / (float)(n_neg + 1));
        float per_row = __logf(5.33f + __expf(pos_loss + neg_loss));
        g_row[row] = (n_neg >= 1 && n_pos >= 1) ? per_row : 0.0f;
    }
}

// -------------------- kernel 4: final reduce (float4 + shuffle) --------------------
__global__ void __launch_bounds__(256) final_reduce_kernel(float* __restrict__ out) {
    __shared__ float wsum[8];
    int tid = threadIdx.x;
    int lid = tid & 31, wrp = tid >> 5;
    const float4* r4 = reinterpret_cast<const float4*>(g_row);
    float s = 0.0f;
#pragma unroll
    for (int it = 0; it < 4; it++) {
        float4 v = r4[it * 256 + tid];
        s += (v.x + v.y) + (v.z + v.w);
    }
#pragma unroll
    for (int o = 16; o > 0; o >>= 1) s += __shfl_xor_sync(0xFFFFFFFFu, s, o);
    if (lid == 0) wsum[wrp] = s;
    __syncthreads();
    if (tid == 0) {
        float t = 0.0f;
#pragma unroll
        for (int w = 0; w < 8; w++) t += wsum[w];
        out[0] = t * (1.0f / (float)NB);
    }
}

// ---------------------------------------------------------------------------
extern "C" void kernel_launch(void* const* d_in, const int* in_sizes, int n_in,
                              void* d_out, int out_size) {
    const float* feats = (const float*)d_in[0];
    const int* labels = (const int*)d_in[1];
    float* out = (float*)d_out;

    cudaFuncSetAttribute(gemm_mma_kernel,
                         cudaFuncAttributeMaxDynamicSharedMemorySize, DYNSMEM);

    labels_kernel<<<1, 256>>>(labels);
    convert_kernel<<<2048, 512>>>(feats);            // 4M elems, 1 float4/thread
    gemm_mma_kernel<<<dim3(32, 32), 128, DYNSMEM>>>();
    row_kernel<<<NB, 256>>>();
    final_reduce_kernel<<<1, 256>>>(out);
}